// round 15
// baseline (speedup 1.0000x reference)
#include <cuda_runtime.h>
#include <cuda_fp16.h>
#include <cstdint>

#define BATCH 64
#define WAY   5
#define DIM   64
#define NQ    1024
#define NS    1024
#define QTILE 128
#define SCHUNK 128
#define NCHUNK (NS / SCHUNK)
#define NTILES (BATCH * WAY * (NQ / QTILE))   // 2560
#define PGRID  444                             // 148 SMs x 3 CTAs (ALL resident)
#define NSUNIT (BATCH * WAY)                   // 320 S prep units
#define NQUNIT BATCH                           // 64 Q prep units

// fp16 normalized scratch
__device__ __half g_qn[BATCH * NQ * DIM];          // [b][q][d]   8 MB
__device__ __half g_sn[BATCH * WAY * NS * DIM];    // [b][w][s][d] 40 MB
// monotonic counters (never reset -> graph-replay safe)
__device__ unsigned g_qdone[NQUNIT];
__device__ unsigned g_sdone[NSUNIT];
__device__ unsigned g_epoch;
__device__ unsigned g_done;
__device__ unsigned g_ticket;

// smem layout (bytes): rows padded to 144B (72 halves) for conflict-free frag loads
#define SROWB 144
#define A_OFF 0
#define B_OFF (QTILE * SROWB)            // 18432
#define BBUF  (SCHUNK * SROWB)           // 18432
#define SMEM_BYTES (B_OFF + 2 * BBUF)    // 55296

__device__ __forceinline__ uint32_t smem_u32(const void* p) {
    uint32_t a;
    asm("{ .reg .u64 t; cvta.to.shared.u64 t, %1; cvt.u32.u64 %0, t; }" : "=r"(a) : "l"(p));
    return a;
}
#define CP16(dst, src) \
    asm volatile("cp.async.cg.shared.global [%0], [%1], 16;" :: "r"(dst), "l"(src))
#define CP_COMMIT() asm volatile("cp.async.commit_group;" ::: "memory")
#define CP_WAIT(n)  asm volatile("cp.async.wait_group %0;" :: "n"(n) : "memory")

#define LDSM4(r, addr)                                                          \
    asm volatile("ldmatrix.sync.aligned.m8n8.x4.shared.b16 {%0,%1,%2,%3}, [%4];"\
                 : "=r"((r)[0]), "=r"((r)[1]), "=r"((r)[2]), "=r"((r)[3])       \
                 : "r"(addr))

#define MMA16816H(d0,d1, a0,a1,a2,a3, b0,b1)                                    \
    asm volatile("mma.sync.aligned.m16n8k16.row.col.f16.f16.f16.f16 "           \
                 "{%0,%1}, {%2,%3,%4,%5}, {%6,%7}, {%0,%1};"                    \
                 : "+r"(d0), "+r"(d1)                                            \
                 : "r"(a0), "r"(a1), "r"(a2), "r"(a3), "r"(b0), "r"(b1))

#define INS3(t0, t1, t2, s) do {                 \
    float _m0 = fmaxf(t0, s), _l0 = fminf(t0, s);\
    float _m1 = fmaxf(t1, _l0), _l1 = fminf(t1, _l0); \
    t2 = fmaxf(t2, _l1); t1 = _m1; t0 = _m0;     \
} while (0)

#define INS3H(t0, t1, t2, s) do {                          \
    __half2 _m0 = __hmax2(t0, s), _l0 = __hmin2(t0, s);    \
    __half2 _m1 = __hmax2(t1, _l0), _l1 = __hmin2(t1, _l0);\
    t2 = __hmax2(t2, _l1); t1 = _m1; t0 = _m0;             \
} while (0)

__device__ __forceinline__ void norm_row_to_fp16(const float* __restrict__ src,
                                                 uint4* __restrict__ dst) {
    float v[DIM]; float ss = 0.0f;
#pragma unroll
    for (int d = 0; d < DIM; ++d) { v[d] = src[(size_t)d * 1024]; ss = fmaf(v[d], v[d], ss); }
    float rn = 1.0f / fmaxf(sqrtf(ss), 1e-12f);
#pragma unroll
    for (int i = 0; i < 8; ++i) {
        uint32_t u[4];
#pragma unroll
        for (int j = 0; j < 4; ++j) {
            __half2 h = __float22half2_rn(make_float2(v[i*8 + j*2] * rn, v[i*8 + j*2 + 1] * rn));
            u[j] = *(uint32_t*)&h;
        }
        dst[i] = make_uint4(u[0], u[1], u[2], u[3]);
    }
}

__global__ void __launch_bounds__(256, 3) knn_all(const float* __restrict__ qf,
                                                  const float* __restrict__ sf,
                                                  float* __restrict__ out) {
    extern __shared__ char dsm[];
    __shared__ float red[4];
    __shared__ float xm[4][32][3];
    __shared__ unsigned s_tile;
    __shared__ unsigned s_epoch;

    const int tid  = threadIdx.x;
    const int lane = tid & 31;
    const int wid  = tid >> 5;
    const int warpM = wid & 3;
    const int warpN = wid >> 2;
    const int bid  = blockIdx.x;
    const uint32_t sbase = smem_u32(dsm);

    if (tid == 0) s_epoch = atomicAdd(&g_epoch, 0u);
    __syncthreads();
    const unsigned epoch = s_epoch;

    // ================= phase 1: prep (one unit per CTA, bid < 384) ==========
    if (bid < NQUNIT) {
        const int b = bid;
#pragma unroll
        for (int i = 0; i < 4; ++i) {
            int q = i * 256 + tid;
            norm_row_to_fp16(qf + (size_t)b * DIM * NQ + q,
                             (uint4*)(g_qn + ((size_t)b * NQ + q) * DIM));
        }
        __threadfence();
        __syncthreads();
        if (tid == 0) atomicAdd(&g_qdone[b], 1u);
    } else if (bid < NQUNIT + NSUNIT) {
        const int bw = bid - NQUNIT;
#pragma unroll
        for (int i = 0; i < 4; ++i) {
            int s = i * 256 + tid;
            norm_row_to_fp16(sf + (size_t)bw * DIM * NS + s,
                             (uint4*)(g_sn + ((size_t)bw * NS + s) * DIM));
        }
        __threadfence();
        __syncthreads();
        if (tid == 0) {
            out[bw] = 0.0f;          // flag implies out is zeroed
            __threadfence();
            atomicAdd(&g_sdone[bw], 1u);
        }
    }

    // ================= phase 2: MMA + fused top-3 ===========================
    while (true) {
        if (tid == 0) s_tile = atomicAdd(&g_ticket, 1u);
        __syncthreads();
        const unsigned tile = s_tile;
        if (tile >= NTILES) break;

        const int qt = tile & 7;
        const int bw = tile >> 3;
        const int w  = bw % WAY;
        const int b  = bw / WAY;

        // wait for this tile's data (producers are resident peer CTAs)
        if (tid == 0) {
            while (atomicAdd(&g_sdone[bw], 0u) <= epoch) __nanosleep(100);
            while (atomicAdd(&g_qdone[b], 0u) <= epoch) __nanosleep(100);
        }
        __syncthreads();

        const __half* Ag = g_qn + ((size_t)b * NQ + (size_t)qt * QTILE) * DIM;
        const __half* Sg = g_sn + (size_t)(b * WAY + w) * NS * DIM;

        // ---- stage A tile via cp.async
#pragma unroll
        for (int i = 0; i < 4; ++i) {
            int idx = i * 256 + tid;
            int r = idx >> 3, seg = idx & 7;
            CP16(sbase + A_OFF + r * SROWB + seg * 16, Ag + r * DIM + seg * 8);
        }
        CP_COMMIT();
#pragma unroll
        for (int i = 0; i < 4; ++i) {
            int idx = i * 256 + tid;
            int r = idx >> 3, seg = idx & 7;
            CP16(sbase + B_OFF + r * SROWB + seg * 16, Sg + r * DIM + seg * 8);
        }
        CP_COMMIT();

        CP_WAIT(1);
        __syncthreads();

        uint32_t a[2][4][4];
#pragma unroll
        for (int mt = 0; mt < 2; ++mt) {
            uint32_t rbase = sbase + A_OFF
                           + (uint32_t)(warpM * 32 + mt * 16 + (lane & 15)) * SROWB
                           + (uint32_t)(lane >> 4) * 16;
            LDSM4(a[mt][0], rbase);
            LDSM4(a[mt][1], rbase + 32);
            LDSM4(a[mt][2], rbase + 64);
            LDSM4(a[mt][3], rbase + 96);
        }

        const __half2 NEGINF = __halves2half2(__ushort_as_half(0xFC00), __ushort_as_half(0xFC00));
        __half2 t[4][3];
#pragma unroll
        for (int r = 0; r < 4; ++r) { t[r][0] = NEGINF; t[r][1] = NEGINF; t[r][2] = NEGINF; }

        for (int ch = 0; ch < NCHUNK; ++ch) {
            const int cur = ch & 1;
            __syncthreads();
            if (ch + 1 < NCHUNK) {
                const __half* src = Sg + (size_t)(ch + 1) * SCHUNK * DIM;
                uint32_t dstb = sbase + B_OFF + (cur ^ 1) * BBUF;
#pragma unroll
                for (int i = 0; i < 4; ++i) {
                    int idx = i * 256 + tid;
                    int r = idx >> 3, seg = idx & 7;
                    CP16(dstb + r * SROWB + seg * 16, src + r * DIM + seg * 8);
                }
                CP_COMMIT();
                CP_WAIT(1);
            } else {
                CP_WAIT(0);
            }
            __syncthreads();

            const uint32_t ldsm_base = sbase + B_OFF + cur * BBUF
                                     + (uint32_t)(warpN * 64 + (lane & 7)) * SROWB
                                     + (uint32_t)(lane >> 3) * 16;

#pragma unroll 2
            for (int nt = 0; nt < 8; nt += 2) {
                const uint32_t addr0 = ldsm_base + (uint32_t)(nt * 8) * SROWB;
                const uint32_t addr1 = addr0 + 8 * SROWB;
                uint32_t bA[4], bB[4], bC[4], bD[4];
                LDSM4(bA, addr0);
                LDSM4(bB, addr0 + 64);
                LDSM4(bC, addr1);
                LDSM4(bD, addr1 + 64);

                uint32_t d00 = 0, d01 = 0, d02 = 0, d03 = 0;
                uint32_t d10 = 0, d11 = 0, d12 = 0, d13 = 0;

                MMA16816H(d00, d01, a[0][0][0], a[0][0][1], a[0][0][2], a[0][0][3], bA[0], bA[1]);
                MMA16816H(d02, d03, a[1][0][0], a[1][0][1], a[1][0][2], a[1][0][3], bA[0], bA[1]);
                MMA16816H(d10, d11, a[0][0][0], a[0][0][1], a[0][0][2], a[0][0][3], bC[0], bC[1]);
                MMA16816H(d12, d13, a[1][0][0], a[1][0][1], a[1][0][2], a[1][0][3], bC[0], bC[1]);

                MMA16816H(d00, d01, a[0][1][0], a[0][1][1], a[0][1][2], a[0][1][3], bA[2], bA[3]);
                MMA16816H(d02, d03, a[1][1][0], a[1][1][1], a[1][1][2], a[1][1][3], bA[2], bA[3]);
                MMA16816H(d10, d11, a[0][1][0], a[0][1][1], a[0][1][2], a[0][1][3], bC[2], bC[3]);
                MMA16816H(d12, d13, a[1][1][0], a[1][1][1], a[1][1][2], a[1][1][3], bC[2], bC[3]);

                MMA16816H(d00, d01, a[0][2][0], a[0][2][1], a[0][2][2], a[0][2][3], bB[0], bB[1]);
                MMA16816H(d02, d03, a[1][2][0], a[1][2][1], a[1][2][2], a[1][2][3], bB[0], bB[1]);
                MMA16816H(d10, d11, a[0][2][0], a[0][2][1], a[0][2][2], a[0][2][3], bD[0], bD[1]);
                MMA16816H(d12, d13, a[1][2][0], a[1][2][1], a[1][2][2], a[1][2][3], bD[0], bD[1]);

                MMA16816H(d00, d01, a[0][3][0], a[0][3][1], a[0][3][2], a[0][3][3], bB[2], bB[3]);
                MMA16816H(d02, d03, a[1][3][0], a[1][3][1], a[1][3][2], a[1][3][3], bB[2], bB[3]);
                MMA16816H(d10, d11, a[0][3][0], a[0][3][1], a[0][3][2], a[0][3][3], bD[2], bD[3]);
                MMA16816H(d12, d13, a[1][3][0], a[1][3][1], a[1][3][2], a[1][3][3], bD[2], bD[3]);

                INS3H(t[0][0], t[0][1], t[0][2], *(__half2*)&d00);
                INS3H(t[1][0], t[1][1], t[1][2], *(__half2*)&d01);
                INS3H(t[2][0], t[2][1], t[2][2], *(__half2*)&d02);
                INS3H(t[3][0], t[3][1], t[3][2], *(__half2*)&d03);
                INS3H(t[0][0], t[0][1], t[0][2], *(__half2*)&d10);
                INS3H(t[1][0], t[1][1], t[1][2], *(__half2*)&d11);
                INS3H(t[2][0], t[2][1], t[2][2], *(__half2*)&d12);
                INS3H(t[3][0], t[3][1], t[3][2], *(__half2*)&d13);
            }
        }

        // ---- merge top-3 across the 4 lanes sharing each row
#pragma unroll
        for (int r = 0; r < 4; ++r) {
#pragma unroll
            for (int d = 1; d <= 2; d <<= 1) {
                __half2 r0, r1, r2;
                *(uint32_t*)&r0 = __shfl_xor_sync(0xFFFFFFFFu, *(uint32_t*)&t[r][0], d);
                *(uint32_t*)&r1 = __shfl_xor_sync(0xFFFFFFFFu, *(uint32_t*)&t[r][1], d);
                *(uint32_t*)&r2 = __shfl_xor_sync(0xFFFFFFFFu, *(uint32_t*)&t[r][2], d);
                INS3H(t[r][0], t[r][1], t[r][2], r0);
                INS3H(t[r][0], t[r][1], t[r][2], r1);
                INS3H(t[r][0], t[r][1], t[r][2], r2);
            }
        }

        // ---- unpack parity streams, per-row f32 top-3
        float f[4][3];
#pragma unroll
        for (int r = 0; r < 4; ++r) {
            f[r][0] = -1e30f; f[r][1] = -1e30f; f[r][2] = -1e30f;
#pragma unroll
            for (int k = 0; k < 3; ++k) {
                INS3(f[r][0], f[r][1], f[r][2], __low2float(t[r][k]));
                INS3(f[r][0], f[r][1], f[r][2], __high2float(t[r][k]));
            }
        }

        // ---- merge across warpN halves
        const int gid = lane >> 2;
        if (warpN == 1 && (lane & 3) == 0) {
#pragma unroll
            for (int r = 0; r < 4; ++r) {
                int row = (r >> 1) * 16 + (r & 1) * 8 + gid;
                xm[warpM][row][0] = f[r][0];
                xm[warpM][row][1] = f[r][1];
                xm[warpM][row][2] = f[r][2];
            }
        }
        __syncthreads();

        if (warpN == 0) {
            float local = 0.0f;
            if ((lane & 3) == 0) {
#pragma unroll
                for (int r = 0; r < 4; ++r) {
                    int row = (r >> 1) * 16 + (r & 1) * 8 + gid;
                    INS3(f[r][0], f[r][1], f[r][2], xm[warpM][row][0]);
                    INS3(f[r][0], f[r][1], f[r][2], xm[warpM][row][1]);
                    INS3(f[r][0], f[r][1], f[r][2], xm[warpM][row][2]);
                    local += f[r][0] + f[r][1] + f[r][2];
                }
            }
#pragma unroll
            for (int off = 16; off > 0; off >>= 1)
                local += __shfl_down_sync(0xFFFFFFFFu, local, off);
            if (lane == 0) red[warpM] = local;
        }
        __syncthreads();
        if (tid == 0) {
            atomicAdd(&out[b * WAY + w], red[0] + red[1] + red[2] + red[3]);
        }
        __syncthreads();
    }

    // ---- end of launch: last CTA resets tile ticket, bumps epoch ----------
    if (tid == 0) {
        __threadfence();
        unsigned fin = atomicAdd(&g_done, 1u);
        if ((fin % PGRID) == PGRID - 1u) {
            atomicExch(&g_ticket, 0u);
            atomicAdd(&g_epoch, 1u);
        }
    }
}

extern "C" void kernel_launch(void* const* d_in, const int* in_sizes, int n_in,
                              void* d_out, int out_size) {
    const float* qf = (const float*)d_in[0];   // (64, 64, 32, 32)
    const float* sf = (const float*)d_in[1];   // (64, 5, 64, 1024)
    float* out = (float*)d_out;                // (64, 5)

    cudaFuncSetAttribute(knn_all, cudaFuncAttributeMaxDynamicSharedMemorySize, SMEM_BYTES);

    knn_all<<<PGRID, 256, SMEM_BYTES>>>(qf, sf, out);
}

// round 16
// speedup vs baseline: 1.0594x; 1.0594x over previous
#include <cuda_runtime.h>
#include <cuda_fp16.h>
#include <cstdint>

#define BATCH 64
#define WAY   5
#define DIM   64
#define NQ    1024
#define NS    1024
#define QTILE 128
#define SCHUNK 128
#define NCHUNK (NS / SCHUNK)
#define NTILES (BATCH * WAY * (NQ / QTILE))   // 2560
#define PGRID  592                             // 148 SMs x 4 CTAs

// fp16 normalized scratch
__device__ __half g_qn[BATCH * NQ * DIM];          // [b][q][d]   8 MB
__device__ __half g_sn[BATCH * WAY * NS * DIM];    // [b][w][s][d] 40 MB
__device__ unsigned g_ticket;

// smem layout (bytes): rows padded to 144B (72 halves) for conflict-free frag loads
#define SROWB 144
#define A_OFF 0
#define B_OFF (QTILE * SROWB)            // 18432
#define BBUF  (SCHUNK * SROWB)           // 18432
#define SMEM_BYTES (B_OFF + 2 * BBUF)    // 55296

__device__ __forceinline__ uint32_t smem_u32(const void* p) {
    uint32_t a;
    asm("{ .reg .u64 t; cvta.to.shared.u64 t, %1; cvt.u32.u64 %0, t; }" : "=r"(a) : "l"(p));
    return a;
}
#define CP16(dst, src) \
    asm volatile("cp.async.cg.shared.global [%0], [%1], 16;" :: "r"(dst), "l"(src))
#define CP_COMMIT() asm volatile("cp.async.commit_group;" ::: "memory")
#define CP_WAIT(n)  asm volatile("cp.async.wait_group %0;" :: "n"(n) : "memory")

#define LDSM4(r, addr)                                                          \
    asm volatile("ldmatrix.sync.aligned.m8n8.x4.shared.b16 {%0,%1,%2,%3}, [%4];"\
                 : "=r"((r)[0]), "=r"((r)[1]), "=r"((r)[2]), "=r"((r)[3])       \
                 : "r"(addr))

#define MMA16816H(d0,d1, a0,a1,a2,a3, b0,b1)                                    \
    asm volatile("mma.sync.aligned.m16n8k16.row.col.f16.f16.f16.f16 "           \
                 "{%0,%1}, {%2,%3,%4,%5}, {%6,%7}, {%0,%1};"                    \
                 : "+r"(d0), "+r"(d1)                                            \
                 : "r"(a0), "r"(a1), "r"(a2), "r"(a3), "r"(b0), "r"(b1))

#define INS3(t0, t1, t2, s) do {                 \
    float _m0 = fmaxf(t0, s), _l0 = fminf(t0, s);\
    float _m1 = fmaxf(t1, _l0), _l1 = fminf(t1, _l0); \
    t2 = fmaxf(t2, _l1); t1 = _m1; t0 = _m0;     \
} while (0)

#define INS3H(t0, t1, t2, s) do {                          \
    __half2 _m0 = __hmax2(t0, s), _l0 = __hmin2(t0, s);    \
    __half2 _m1 = __hmax2(t1, _l0), _l1 = __hmin2(t1, _l0);\
    t2 = __hmax2(t2, _l1); t1 = _m1; t0 = _m0;             \
} while (0)

// ---- fused setup: zero out, reset ticket, normalize Q and S into fp16 scratch
__global__ void __launch_bounds__(256) prep_all(const float* __restrict__ qf,
                                                const float* __restrict__ sf,
                                                float* __restrict__ out) {
    const int blk = blockIdx.x;
    const int tid = threadIdx.x;
    if (blk == 0 && tid == 0) g_ticket = 0;
    if (blk < 2) {
        int i = blk * 256 + tid;
        if (i < BATCH * WAY) out[i] = 0.0f;
    }
    float v[DIM]; float ss = 0.0f;
    uint4* dst;
    if (blk < 256) {
        int q = (blk & 3) * 256 + tid;
        int b = blk >> 2;
        const float* src = qf + (size_t)b * DIM * NQ + q;
#pragma unroll
        for (int d = 0; d < DIM; ++d) { v[d] = src[(size_t)d * NQ]; ss = fmaf(v[d], v[d], ss); }
        dst = (uint4*)(g_qn + ((size_t)b * NQ + q) * DIM);
    } else {
        int sb = blk - 256;
        int s = (sb & 3) * 256 + tid;
        int w = (sb >> 2) % WAY;
        int b = (sb >> 2) / WAY;
        size_t bw = (size_t)b * WAY + w;
        const float* src = sf + bw * DIM * NS + s;
#pragma unroll
        for (int d = 0; d < DIM; ++d) { v[d] = src[(size_t)d * NS]; ss = fmaf(v[d], v[d], ss); }
        dst = (uint4*)(g_sn + (bw * NS + s) * DIM);
    }
    float rn = 1.0f / fmaxf(sqrtf(ss), 1e-12f);
#pragma unroll
    for (int i = 0; i < 8; ++i) {
        uint32_t u[4];
#pragma unroll
        for (int j = 0; j < 4; ++j) {
            __half2 h = __float22half2_rn(make_float2(v[i*8 + j*2] * rn, v[i*8 + j*2 + 1] * rn));
            u[j] = *(uint32_t*)&h;
        }
        dst[i] = make_uint4(u[0], u[1], u[2], u[3]);
    }
}

__global__ void __launch_bounds__(256, 4) knn_mma(float* __restrict__ out) {
    extern __shared__ char dsm[];
    __shared__ float red[4];
    __shared__ float xm[4][32][3];
    __shared__ unsigned s_tile;

    const int tid  = threadIdx.x;
    const int lane = tid & 31;
    const int wid  = tid >> 5;
    const int warpM = wid & 3;        // 4 warps along M (32 rows each)
    const int warpN = wid >> 2;       // 2 warps along N (64 cols each)

    const uint32_t sbase = smem_u32(dsm);

    while (true) {
        if (tid == 0) s_tile = atomicAdd(&g_ticket, 1u);
        __syncthreads();
        const unsigned tile = s_tile;
        if (tile >= NTILES) break;

        const int qt = tile & 7;             // qt fastest: concurrent tiles share S in L2
        const int bw = tile >> 3;
        const int w  = bw % WAY;
        const int b  = bw / WAY;

        const __half* Ag = g_qn + ((size_t)b * NQ + (size_t)qt * QTILE) * DIM;
        const __half* Sg = g_sn + (size_t)(b * WAY + w) * NS * DIM;

        // ---- stage A tile (128 x 64 fp16) via cp.async, group 0
#pragma unroll
        for (int i = 0; i < 4; ++i) {
            int idx = i * 256 + tid;
            int r = idx >> 3, seg = idx & 7;
            CP16(sbase + A_OFF + r * SROWB + seg * 16, Ag + r * DIM + seg * 8);
        }
        CP_COMMIT();
        // ---- stage S chunk 0 into buf 0
#pragma unroll
        for (int i = 0; i < 4; ++i) {
            int idx = i * 256 + tid;
            int r = idx >> 3, seg = idx & 7;
            CP16(sbase + B_OFF + r * SROWB + seg * 16, Sg + r * DIM + seg * 8);
        }
        CP_COMMIT();

        CP_WAIT(1);            // A ready
        __syncthreads();

        // ---- A fragments via ldmatrix: a[mt][kt][4]
        uint32_t a[2][4][4];
#pragma unroll
        for (int mt = 0; mt < 2; ++mt) {
            uint32_t rbase = sbase + A_OFF
                           + (uint32_t)(warpM * 32 + mt * 16 + (lane & 15)) * SROWB
                           + (uint32_t)(lane >> 4) * 16;
            LDSM4(a[mt][0], rbase);
            LDSM4(a[mt][1], rbase + 32);
            LDSM4(a[mt][2], rbase + 64);
            LDSM4(a[mt][3], rbase + 96);
        }

        const __half2 NEGINF = __halves2half2(__ushort_as_half(0xFC00), __ushort_as_half(0xFC00));
        __half2 t[4][3];
#pragma unroll
        for (int r = 0; r < 4; ++r) { t[r][0] = NEGINF; t[r][1] = NEGINF; t[r][2] = NEGINF; }

        for (int ch = 0; ch < NCHUNK; ++ch) {
            const int cur = ch & 1;
            __syncthreads();
            if (ch + 1 < NCHUNK) {
                const __half* src = Sg + (size_t)(ch + 1) * SCHUNK * DIM;
                uint32_t dstb = sbase + B_OFF + (cur ^ 1) * BBUF;
#pragma unroll
                for (int i = 0; i < 4; ++i) {
                    int idx = i * 256 + tid;
                    int r = idx >> 3, seg = idx & 7;
                    CP16(dstb + r * SROWB + seg * 16, src + r * DIM + seg * 8);
                }
                CP_COMMIT();
                CP_WAIT(1);
            } else {
                CP_WAIT(0);
            }
            __syncthreads();

            const uint32_t ldsm_base = sbase + B_OFF + cur * BBUF
                                     + (uint32_t)(warpN * 64 + (lane & 7)) * SROWB
                                     + (uint32_t)(lane >> 3) * 16;

#pragma unroll 2
            for (int nt = 0; nt < 8; nt += 2) {
                const uint32_t addr0 = ldsm_base + (uint32_t)(nt * 8) * SROWB;
                const uint32_t addr1 = addr0 + 8 * SROWB;
                uint32_t bA[4], bB[4], bC[4], bD[4];
                LDSM4(bA, addr0);        // nt+0: kt0, kt1
                LDSM4(bB, addr0 + 64);   // nt+0: kt2, kt3
                LDSM4(bC, addr1);        // nt+1: kt0, kt1
                LDSM4(bD, addr1 + 64);   // nt+1: kt2, kt3

                uint32_t d00 = 0, d01 = 0, d02 = 0, d03 = 0;
                uint32_t d10 = 0, d11 = 0, d12 = 0, d13 = 0;

                MMA16816H(d00, d01, a[0][0][0], a[0][0][1], a[0][0][2], a[0][0][3], bA[0], bA[1]);
                MMA16816H(d02, d03, a[1][0][0], a[1][0][1], a[1][0][2], a[1][0][3], bA[0], bA[1]);
                MMA16816H(d10, d11, a[0][0][0], a[0][0][1], a[0][0][2], a[0][0][3], bC[0], bC[1]);
                MMA16816H(d12, d13, a[1][0][0], a[1][0][1], a[1][0][2], a[1][0][3], bC[0], bC[1]);

                MMA16816H(d00, d01, a[0][1][0], a[0][1][1], a[0][1][2], a[0][1][3], bA[2], bA[3]);
                MMA16816H(d02, d03, a[1][1][0], a[1][1][1], a[1][1][2], a[1][1][3], bA[2], bA[3]);
                MMA16816H(d10, d11, a[0][1][0], a[0][1][1], a[0][1][2], a[0][1][3], bC[2], bC[3]);
                MMA16816H(d12, d13, a[1][1][0], a[1][1][1], a[1][1][2], a[1][1][3], bC[2], bC[3]);

                MMA16816H(d00, d01, a[0][2][0], a[0][2][1], a[0][2][2], a[0][2][3], bB[0], bB[1]);
                MMA16816H(d02, d03, a[1][2][0], a[1][2][1], a[1][2][2], a[1][2][3], bB[0], bB[1]);
                MMA16816H(d10, d11, a[0][2][0], a[0][2][1], a[0][2][2], a[0][2][3], bD[0], bD[1]);
                MMA16816H(d12, d13, a[1][2][0], a[1][2][1], a[1][2][2], a[1][2][3], bD[0], bD[1]);

                MMA16816H(d00, d01, a[0][3][0], a[0][3][1], a[0][3][2], a[0][3][3], bB[2], bB[3]);
                MMA16816H(d02, d03, a[1][3][0], a[1][3][1], a[1][3][2], a[1][3][3], bB[2], bB[3]);
                MMA16816H(d10, d11, a[0][3][0], a[0][3][1], a[0][3][2], a[0][3][3], bD[2], bD[3]);
                MMA16816H(d12, d13, a[1][3][0], a[1][3][1], a[1][3][2], a[1][3][3], bD[2], bD[3]);

                INS3H(t[0][0], t[0][1], t[0][2], *(__half2*)&d00);
                INS3H(t[1][0], t[1][1], t[1][2], *(__half2*)&d01);
                INS3H(t[2][0], t[2][1], t[2][2], *(__half2*)&d02);
                INS3H(t[3][0], t[3][1], t[3][2], *(__half2*)&d03);
                INS3H(t[0][0], t[0][1], t[0][2], *(__half2*)&d10);
                INS3H(t[1][0], t[1][1], t[1][2], *(__half2*)&d11);
                INS3H(t[2][0], t[2][1], t[2][2], *(__half2*)&d12);
                INS3H(t[3][0], t[3][1], t[3][2], *(__half2*)&d13);
            }
        }

        // ---- merge top-3 across the 4 lanes sharing each row (half2 domain)
#pragma unroll
        for (int r = 0; r < 4; ++r) {
#pragma unroll
            for (int d = 1; d <= 2; d <<= 1) {
                __half2 r0, r1, r2;
                *(uint32_t*)&r0 = __shfl_xor_sync(0xFFFFFFFFu, *(uint32_t*)&t[r][0], d);
                *(uint32_t*)&r1 = __shfl_xor_sync(0xFFFFFFFFu, *(uint32_t*)&t[r][1], d);
                *(uint32_t*)&r2 = __shfl_xor_sync(0xFFFFFFFFu, *(uint32_t*)&t[r][2], d);
                INS3H(t[r][0], t[r][1], t[r][2], r0);
                INS3H(t[r][0], t[r][1], t[r][2], r1);
                INS3H(t[r][0], t[r][1], t[r][2], r2);
            }
        }

        // ---- merge the 2 parity streams in half2 domain (byte_perm swap, exact;
        //      proven numerically identical in R13): low halves then hold top-3
        //      of the union of both streams.
        float f[4][3];
#pragma unroll
        for (int r = 0; r < 4; ++r) {
            uint32_t u0 = *(uint32_t*)&t[r][0];
            uint32_t u1 = *(uint32_t*)&t[r][1];
            uint32_t u2 = *(uint32_t*)&t[r][2];
            __half2 s0, s1, s2;
            *(uint32_t*)&s0 = __byte_perm(u0, u0, 0x1032);
            *(uint32_t*)&s1 = __byte_perm(u1, u1, 0x1032);
            *(uint32_t*)&s2 = __byte_perm(u2, u2, 0x1032);
            INS3H(t[r][0], t[r][1], t[r][2], s0);
            INS3H(t[r][0], t[r][1], t[r][2], s1);
            INS3H(t[r][0], t[r][1], t[r][2], s2);
            f[r][0] = __low2float(t[r][0]);
            f[r][1] = __low2float(t[r][1]);
            f[r][2] = __low2float(t[r][2]);
        }

        // ---- merge across warpN halves
        const int gid = lane >> 2;
        if (warpN == 1 && (lane & 3) == 0) {
#pragma unroll
            for (int r = 0; r < 4; ++r) {
                int row = (r >> 1) * 16 + (r & 1) * 8 + gid;
                xm[warpM][row][0] = f[r][0];
                xm[warpM][row][1] = f[r][1];
                xm[warpM][row][2] = f[r][2];
            }
        }
        __syncthreads();

        if (warpN == 0) {
            float local = 0.0f;
            if ((lane & 3) == 0) {
#pragma unroll
                for (int r = 0; r < 4; ++r) {
                    int row = (r >> 1) * 16 + (r & 1) * 8 + gid;
                    INS3(f[r][0], f[r][1], f[r][2], xm[warpM][row][0]);
                    INS3(f[r][0], f[r][1], f[r][2], xm[warpM][row][1]);
                    INS3(f[r][0], f[r][1], f[r][2], xm[warpM][row][2]);
                    local += f[r][0] + f[r][1] + f[r][2];
                }
            }
#pragma unroll
            for (int off = 16; off > 0; off >>= 1)
                local += __shfl_down_sync(0xFFFFFFFFu, local, off);
            if (lane == 0) red[warpM] = local;
        }
        __syncthreads();
        if (tid == 0) {
            atomicAdd(&out[b * WAY + w], red[0] + red[1] + red[2] + red[3]);
        }
        __syncthreads();
    }
}

extern "C" void kernel_launch(void* const* d_in, const int* in_sizes, int n_in,
                              void* d_out, int out_size) {
    const float* qf = (const float*)d_in[0];   // (64, 64, 32, 32)
    const float* sf = (const float*)d_in[1];   // (64, 5, 64, 1024)
    float* out = (float*)d_out;                // (64, 5)

    cudaFuncSetAttribute(knn_mma, cudaFuncAttributeMaxDynamicSharedMemorySize, SMEM_BYTES);

    prep_all<<<1536, 256>>>(qf, sf, out);
    knn_mma<<<PGRID, 256, SMEM_BYTES>>>(out);
}

// round 17
// speedup vs baseline: 1.0596x; 1.0002x over previous
#include <cuda_runtime.h>
#include <cuda_fp16.h>
#include <cstdint>

#define BATCH 64
#define WAY   5
#define DIM   64
#define NQ    1024
#define NS    1024
#define QTILE 128
#define SCHUNK 128
#define NCHUNK (NS / SCHUNK)
#define NTILES (BATCH * WAY * (NQ / QTILE))   // 2560
#define PGRID  592                             // 148 SMs x 4 CTAs

// fp16 normalized scratch
__device__ __half g_qn[BATCH * NQ * DIM];          // [b][q][d]   8 MB
__device__ __half g_sn[BATCH * WAY * NS * DIM];    // [b][w][s][d] 40 MB
__device__ unsigned g_ticket;

// smem layout (bytes): rows padded to 144B (72 halves) for conflict-free frag loads
#define SROWB 144
#define A_OFF 0
#define B_OFF (QTILE * SROWB)            // 18432
#define BBUF  (SCHUNK * SROWB)           // 18432
#define SMEM_BYTES (B_OFF + 2 * BBUF)    // 55296

__device__ __forceinline__ uint32_t smem_u32(const void* p) {
    uint32_t a;
    asm("{ .reg .u64 t; cvta.to.shared.u64 t, %1; cvt.u32.u64 %0, t; }" : "=r"(a) : "l"(p));
    return a;
}
#define CP16(dst, src) \
    asm volatile("cp.async.cg.shared.global [%0], [%1], 16;" :: "r"(dst), "l"(src))
#define CP_COMMIT() asm volatile("cp.async.commit_group;" ::: "memory")
#define CP_WAIT(n)  asm volatile("cp.async.wait_group %0;" :: "n"(n) : "memory")

#define LDSM4(r, addr)                                                          \
    asm volatile("ldmatrix.sync.aligned.m8n8.x4.shared.b16 {%0,%1,%2,%3}, [%4];"\
                 : "=r"((r)[0]), "=r"((r)[1]), "=r"((r)[2]), "=r"((r)[3])       \
                 : "r"(addr))

#define MMA16816H(d0,d1, a0,a1,a2,a3, b0,b1)                                    \
    asm volatile("mma.sync.aligned.m16n8k16.row.col.f16.f16.f16.f16 "           \
                 "{%0,%1}, {%2,%3,%4,%5}, {%6,%7}, {%0,%1};"                    \
                 : "+r"(d0), "+r"(d1)                                            \
                 : "r"(a0), "r"(a1), "r"(a2), "r"(a3), "r"(b0), "r"(b1))

#define INS3(t0, t1, t2, s) do {                 \
    float _m0 = fmaxf(t0, s), _l0 = fminf(t0, s);\
    float _m1 = fmaxf(t1, _l0), _l1 = fminf(t1, _l0); \
    t2 = fmaxf(t2, _l1); t1 = _m1; t0 = _m0;     \
} while (0)

#define INS3H(t0, t1, t2, s) do {                          \
    __half2 _m0 = __hmax2(t0, s), _l0 = __hmin2(t0, s);    \
    __half2 _m1 = __hmax2(t1, _l0), _l1 = __hmin2(t1, _l0);\
    t2 = __hmax2(t2, _l1); t1 = _m1; t0 = _m0;             \
} while (0)

// ---- fused setup: zero out, reset ticket, normalize Q and S into fp16 scratch
__global__ void __launch_bounds__(256) prep_all(const float* __restrict__ qf,
                                                const float* __restrict__ sf,
                                                float* __restrict__ out) {
    const int blk = blockIdx.x;
    const int tid = threadIdx.x;
    if (blk == 0 && tid == 0) g_ticket = 0;
    if (blk < 2) {
        int i = blk * 256 + tid;
        if (i < BATCH * WAY) out[i] = 0.0f;
    }
    float v[DIM]; float ss = 0.0f;
    uint4* dst;
    if (blk < 256) {
        int q = (blk & 3) * 256 + tid;
        int b = blk >> 2;
        const float* src = qf + (size_t)b * DIM * NQ + q;
#pragma unroll
        for (int d = 0; d < DIM; ++d) { v[d] = src[(size_t)d * NQ]; ss = fmaf(v[d], v[d], ss); }
        dst = (uint4*)(g_qn + ((size_t)b * NQ + q) * DIM);
    } else {
        int sb = blk - 256;
        int s = (sb & 3) * 256 + tid;
        int w = (sb >> 2) % WAY;
        int b = (sb >> 2) / WAY;
        size_t bw = (size_t)b * WAY + w;
        const float* src = sf + bw * DIM * NS + s;
#pragma unroll
        for (int d = 0; d < DIM; ++d) { v[d] = src[(size_t)d * NS]; ss = fmaf(v[d], v[d], ss); }
        dst = (uint4*)(g_sn + (bw * NS + s) * DIM);
    }
    float rn = 1.0f / fmaxf(sqrtf(ss), 1e-12f);
#pragma unroll
    for (int i = 0; i < 8; ++i) {
        uint32_t u[4];
#pragma unroll
        for (int j = 0; j < 4; ++j) {
            __half2 h = __float22half2_rn(make_float2(v[i*8 + j*2] * rn, v[i*8 + j*2 + 1] * rn));
            u[j] = *(uint32_t*)&h;
        }
        dst[i] = make_uint4(u[0], u[1], u[2], u[3]);
    }
}

__global__ void __launch_bounds__(256, 4) knn_mma(float* __restrict__ out) {
    extern __shared__ char dsm[];
    __shared__ float red[4];
    __shared__ float xm[4][32][3];
    __shared__ unsigned s_tile;

    const int tid  = threadIdx.x;
    const int lane = tid & 31;
    const int wid  = tid >> 5;
    const int warpM = wid & 3;        // 4 warps along M (32 rows each)
    const int warpN = wid >> 2;       // 2 warps along N (64 cols each)

    const uint32_t sbase = smem_u32(dsm);

    while (true) {
        if (tid == 0) s_tile = atomicAdd(&g_ticket, 1u);
        __syncthreads();
        const unsigned tile = s_tile;
        if (tile >= NTILES) break;

        const int qt = tile & 7;             // qt fastest: concurrent tiles share S in L2
        const int bw = tile >> 3;
        const int w  = bw % WAY;
        const int b  = bw / WAY;

        const __half* Ag = g_qn + ((size_t)b * NQ + (size_t)qt * QTILE) * DIM;
        const __half* Sg = g_sn + (size_t)(b * WAY + w) * NS * DIM;

        // ---- stage A tile (128 x 64 fp16) via cp.async, group 0
#pragma unroll
        for (int i = 0; i < 4; ++i) {
            int idx = i * 256 + tid;
            int r = idx >> 3, seg = idx & 7;
            CP16(sbase + A_OFF + r * SROWB + seg * 16, Ag + r * DIM + seg * 8);
        }
        CP_COMMIT();
        // ---- stage S chunk 0 into buf 0
#pragma unroll
        for (int i = 0; i < 4; ++i) {
            int idx = i * 256 + tid;
            int r = idx >> 3, seg = idx & 7;
            CP16(sbase + B_OFF + r * SROWB + seg * 16, Sg + r * DIM + seg * 8);
        }
        CP_COMMIT();

        CP_WAIT(1);            // A ready
        __syncthreads();

        // ---- A fragments via ldmatrix: a[mt][kt][4]
        uint32_t a[2][4][4];
#pragma unroll
        for (int mt = 0; mt < 2; ++mt) {
            uint32_t rbase = sbase + A_OFF
                           + (uint32_t)(warpM * 32 + mt * 16 + (lane & 15)) * SROWB
                           + (uint32_t)(lane >> 4) * 16;
            LDSM4(a[mt][0], rbase);
            LDSM4(a[mt][1], rbase + 32);
            LDSM4(a[mt][2], rbase + 64);
            LDSM4(a[mt][3], rbase + 96);
        }

        const __half2 NEGINF = __halves2half2(__ushort_as_half(0xFC00), __ushort_as_half(0xFC00));
        __half2 t[4][3];
#pragma unroll
        for (int r = 0; r < 4; ++r) { t[r][0] = NEGINF; t[r][1] = NEGINF; t[r][2] = NEGINF; }

        for (int ch = 0; ch < NCHUNK; ++ch) {
            const int cur = ch & 1;
            __syncthreads();
            if (ch + 1 < NCHUNK) {
                const __half* src = Sg + (size_t)(ch + 1) * SCHUNK * DIM;
                uint32_t dstb = sbase + B_OFF + (cur ^ 1) * BBUF;
#pragma unroll
                for (int i = 0; i < 4; ++i) {
                    int idx = i * 256 + tid;
                    int r = idx >> 3, seg = idx & 7;
                    CP16(dstb + r * SROWB + seg * 16, src + r * DIM + seg * 8);
                }
                CP_COMMIT();
                CP_WAIT(1);
            } else {
                CP_WAIT(0);
            }
            __syncthreads();

            const uint32_t ldsm_base = sbase + B_OFF + cur * BBUF
                                     + (uint32_t)(warpN * 64 + (lane & 7)) * SROWB
                                     + (uint32_t)(lane >> 3) * 16;

#pragma unroll 2
            for (int nt = 0; nt < 8; nt += 2) {
                const uint32_t addr0 = ldsm_base + (uint32_t)(nt * 8) * SROWB;
                const uint32_t addr1 = addr0 + 8 * SROWB;
                uint32_t bA[4], bB[4], bC[4], bD[4];
                LDSM4(bA, addr0);        // nt+0: kt0, kt1
                LDSM4(bB, addr0 + 64);   // nt+0: kt2, kt3
                LDSM4(bC, addr1);        // nt+1: kt0, kt1
                LDSM4(bD, addr1 + 64);   // nt+1: kt2, kt3

                uint32_t d00 = 0, d01 = 0, d02 = 0, d03 = 0;
                uint32_t d10 = 0, d11 = 0, d12 = 0, d13 = 0;

                MMA16816H(d00, d01, a[0][0][0], a[0][0][1], a[0][0][2], a[0][0][3], bA[0], bA[1]);
                MMA16816H(d02, d03, a[1][0][0], a[1][0][1], a[1][0][2], a[1][0][3], bA[0], bA[1]);
                MMA16816H(d10, d11, a[0][0][0], a[0][0][1], a[0][0][2], a[0][0][3], bC[0], bC[1]);
                MMA16816H(d12, d13, a[1][0][0], a[1][0][1], a[1][0][2], a[1][0][3], bC[0], bC[1]);

                MMA16816H(d00, d01, a[0][1][0], a[0][1][1], a[0][1][2], a[0][1][3], bA[2], bA[3]);
                MMA16816H(d02, d03, a[1][1][0], a[1][1][1], a[1][1][2], a[1][1][3], bA[2], bA[3]);
                MMA16816H(d10, d11, a[0][1][0], a[0][1][1], a[0][1][2], a[0][1][3], bC[2], bC[3]);
                MMA16816H(d12, d13, a[1][1][0], a[1][1][1], a[1][1][2], a[1][1][3], bC[2], bC[3]);

                MMA16816H(d00, d01, a[0][2][0], a[0][2][1], a[0][2][2], a[0][2][3], bB[0], bB[1]);
                MMA16816H(d02, d03, a[1][2][0], a[1][2][1], a[1][2][2], a[1][2][3], bB[0], bB[1]);
                MMA16816H(d10, d11, a[0][2][0], a[0][2][1], a[0][2][2], a[0][2][3], bD[0], bD[1]);
                MMA16816H(d12, d13, a[1][2][0], a[1][2][1], a[1][2][2], a[1][2][3], bD[0], bD[1]);

                MMA16816H(d00, d01, a[0][3][0], a[0][3][1], a[0][3][2], a[0][3][3], bB[2], bB[3]);
                MMA16816H(d02, d03, a[1][3][0], a[1][3][1], a[1][3][2], a[1][3][3], bB[2], bB[3]);
                MMA16816H(d10, d11, a[0][3][0], a[0][3][1], a[0][3][2], a[0][3][3], bD[2], bD[3]);
                MMA16816H(d12, d13, a[1][3][0], a[1][3][1], a[1][3][2], a[1][3][3], bD[2], bD[3]);

                INS3H(t[0][0], t[0][1], t[0][2], *(__half2*)&d00);
                INS3H(t[1][0], t[1][1], t[1][2], *(__half2*)&d01);
                INS3H(t[2][0], t[2][1], t[2][2], *(__half2*)&d02);
                INS3H(t[3][0], t[3][1], t[3][2], *(__half2*)&d03);
                INS3H(t[0][0], t[0][1], t[0][2], *(__half2*)&d10);
                INS3H(t[1][0], t[1][1], t[1][2], *(__half2*)&d11);
                INS3H(t[2][0], t[2][1], t[2][2], *(__half2*)&d12);
                INS3H(t[3][0], t[3][1], t[3][2], *(__half2*)&d13);
            }
        }

        // ---- merge top-3 across the 4 lanes sharing each row (half2 domain)
#pragma unroll
        for (int r = 0; r < 4; ++r) {
#pragma unroll
            for (int d = 1; d <= 2; d <<= 1) {
                __half2 r0, r1, r2;
                *(uint32_t*)&r0 = __shfl_xor_sync(0xFFFFFFFFu, *(uint32_t*)&t[r][0], d);
                *(uint32_t*)&r1 = __shfl_xor_sync(0xFFFFFFFFu, *(uint32_t*)&t[r][1], d);
                *(uint32_t*)&r2 = __shfl_xor_sync(0xFFFFFFFFu, *(uint32_t*)&t[r][2], d);
                INS3H(t[r][0], t[r][1], t[r][2], r0);
                INS3H(t[r][0], t[r][1], t[r][2], r1);
                INS3H(t[r][0], t[r][1], t[r][2], r2);
            }
        }

        // ---- merge the 2 parity streams in half2 domain (byte_perm swap, exact)
        float f[4][3];
#pragma unroll
        for (int r = 0; r < 4; ++r) {
            uint32_t u0 = *(uint32_t*)&t[r][0];
            uint32_t u1 = *(uint32_t*)&t[r][1];
            uint32_t u2 = *(uint32_t*)&t[r][2];
            __half2 s0, s1, s2;
            *(uint32_t*)&s0 = __byte_perm(u0, u0, 0x1032);
            *(uint32_t*)&s1 = __byte_perm(u1, u1, 0x1032);
            *(uint32_t*)&s2 = __byte_perm(u2, u2, 0x1032);
            INS3H(t[r][0], t[r][1], t[r][2], s0);
            INS3H(t[r][0], t[r][1], t[r][2], s1);
            INS3H(t[r][0], t[r][1], t[r][2], s2);
            f[r][0] = __low2float(t[r][0]);
            f[r][1] = __low2float(t[r][1]);
            f[r][2] = __low2float(t[r][2]);
        }

        // ---- merge across warpN halves
        const int gid = lane >> 2;
        if (warpN == 1 && (lane & 3) == 0) {
#pragma unroll
            for (int r = 0; r < 4; ++r) {
                int row = (r >> 1) * 16 + (r & 1) * 8 + gid;
                xm[warpM][row][0] = f[r][0];
                xm[warpM][row][1] = f[r][1];
                xm[warpM][row][2] = f[r][2];
            }
        }
        __syncthreads();

        if (warpN == 0) {
            float local = 0.0f;
            if ((lane & 3) == 0) {
#pragma unroll
                for (int r = 0; r < 4; ++r) {
                    int row = (r >> 1) * 16 + (r & 1) * 8 + gid;
                    INS3(f[r][0], f[r][1], f[r][2], xm[warpM][row][0]);
                    INS3(f[r][0], f[r][1], f[r][2], xm[warpM][row][1]);
                    INS3(f[r][0], f[r][1], f[r][2], xm[warpM][row][2]);
                    local += f[r][0] + f[r][1] + f[r][2];
                }
            }
#pragma unroll
            for (int off = 16; off > 0; off >>= 1)
                local += __shfl_down_sync(0xFFFFFFFFu, local, off);
            if (lane == 0) red[warpM] = local;
        }
        __syncthreads();
        if (tid == 0) {
            atomicAdd(&out[b * WAY + w], red[0] + red[1] + red[2] + red[3]);
        }
        __syncthreads();
    }
}

extern "C" void kernel_launch(void* const* d_in, const int* in_sizes, int n_in,
                              void* d_out, int out_size) {
    const float* qf = (const float*)d_in[0];   // (64, 64, 32, 32)
    const float* sf = (const float*)d_in[1];   // (64, 5, 64, 1024)
    float* out = (float*)d_out;                // (64, 5)

    cudaFuncSetAttribute(knn_mma, cudaFuncAttributeMaxDynamicSharedMemorySize, SMEM_BYTES);

    prep_all<<<1536, 256>>>(qf, sf, out);
    knn_mma<<<PGRID, 256, SMEM_BYTES>>>(out);
}